// round 16
// baseline (speedup 1.0000x reference)
#include <cuda_runtime.h>
#include <math.h>

// Problem constants (fixed by the reference)
#define B_  64
#define S_  8192
#define H_  512
#define STILE 256
#define NTILES (S_ / STILE)    // 32
#define NBLOCKS1 (B_ * NTILES) // 2048

// Scratch (allocation-free: __device__ globals)
__device__ float g_partial[B_ * NTILES * H_];  // 4 MB
__device__ float g_m[B_ * NTILES];
__device__ float g_l[B_ * NTILES];

// Dynamic smem layout (bytes). sm_ctx (16 KB) is ALIASED into the stage
// region: only touched after the main loop, past a __syncthreads(), when all
// cp.async traffic has drained.
#define OFF_HID     0                         // 2048  (128 float4)
#define OFF_SCORES  2048                      // 1024  (8 x 32 floats)
#define OFF_ROWS    3072                      // 256   (8 x 32 bytes)
#define OFF_M       3328                      // 32
#define OFF_L       3360                      // 32
#define OFF_FLAG    3392                      // 32
#define OFF_STAGE   3456                      // 128-aligned
#define STAGE_PER_WARP 12288                  // 3 bufs x 2 rows x 2048 B
#define SMEM_TOTAL  (OFF_STAGE + 8 * STAGE_PER_WARP)  // 101760 B (~99.4 KB)

// evict_last store helpers (pin k2's 6 MB working set in L2)
__device__ __forceinline__ void st_f32_el(float* p, float v,
                                          unsigned long long pol) {
    asm volatile("st.global.L2::cache_hint.f32 [%0], %1, %2;"
                 :: "l"(p), "f"(v), "l"(pol) : "memory");
}

// ---------------------------------------------------------------------------
// Kernel 1 (hot path frozen since R9; fusion permanently locked out).
// One block per (batch, 256-row S-tile). Each warp owns 32 rows; active rows
// compacted via ballot+popc; triple-buffered cp.async pipeline.
// L2 policies: encoder stream = evict_first (R15 win, -3.2us);
// NEW: scores/partials/g_m/g_l stores = evict_last, so kernel 2's reads hit
// L2 instead of DRAM (6 MB << 126 MB L2).
// ---------------------------------------------------------------------------
__global__ __launch_bounds__(256)
void k1_scores_partials(const float* __restrict__ hid,
                        const float* __restrict__ enc,
                        const void* __restrict__ mask,
                        float* __restrict__ scores_out /* = d_out + B*H */)
{
    extern __shared__ char dsm[];
    float4*        sh_hid    = (float4*)(dsm + OFF_HID);
    float*         sm_scores = (float*)(dsm + OFF_SCORES);
    unsigned char* sm_rows   = (unsigned char*)(dsm + OFF_ROWS);
    float*         sm_m      = (float*)(dsm + OFF_M);
    float*         sm_l      = (float*)(dsm + OFF_L);
    int*           sh_flag   = (int*)(dsm + OFF_FLAG);
    float*         sm_ctx    = (float*)(dsm + OFF_STAGE);   // ALIASED w/ stage

    const int b = blockIdx.x / NTILES;
    const int t = blockIdx.x % NTILES;
    const int tid  = threadIdx.x;
    const int warp = tid >> 5;
    const int lane = tid & 31;

    // L2 policies: evict_first for the single-use encoder stream,
    // evict_last for the small outputs k2 re-reads.
    unsigned long long pol_ef, pol_el;
    asm("createpolicy.fractional.L2::evict_first.b64 %0, 1.0;" : "=l"(pol_ef));
    asm("createpolicy.fractional.L2::evict_last.b64 %0, 1.0;"  : "=l"(pol_el));

    // decoder_hidden[b,:] -> smem
    {
        const float4* h4 = (const float4*)(hid + (size_t)b * H_);
        if (tid < H_ / 4) sh_hid[tid] = h4[tid];
    }
    sm_scores[warp * 32 + lane] = -INFINITY;

    // mask width detection: branch-free OR over first 512 words (safe under
    // both layouts; byte-bools give a word>1 with prob 1-(1/8)^512 ~ 1)
    {
        const unsigned int* mw = (const unsigned int*)mask;
        unsigned int v = mw[tid] | mw[tid + 256];
        unsigned any = __any_sync(0xffffffffu, v > 1u);
        if (lane == 0) sh_flag[warp] = any ? 1 : 0;
    }
    __syncthreads();
    const int mask_is_byte = sh_flag[0] | sh_flag[1] | sh_flag[2] | sh_flag[3]
                           | sh_flag[4] | sh_flag[5] | sh_flag[6] | sh_flag[7];

    float4 hv[4];
#pragma unroll
    for (int j = 0; j < 4; ++j) hv[j] = sh_hid[lane + 32 * j];

    // this warp's 32 rows: ballot + parallel compaction into sm_rows
    const int row0 = t * STILE + warp * 32;
    bool keep;
    if (mask_is_byte)
        keep = ((const unsigned char*)mask)[(size_t)b * S_ + row0 + lane] != 0;
    else
        keep = ((const int*)mask)[(size_t)b * S_ + row0 + lane] != 0;
    const unsigned b0 = __ballot_sync(0xffffffffu, keep);
    const unsigned lmask = (lane == 31) ? 0x7fffffffu : ((1u << lane) - 1u);
    if (keep) sm_rows[warp * 32 + __popc(b0 & lmask)] = (unsigned char)lane;
    const int cnt = __popc(b0);
    __syncwarp();

    const char* gbase = (const char*)(enc + ((size_t)b * S_ + row0) * H_);
    char* stage = dsm + OFF_STAGE + warp * STAGE_PER_WARP;

    float acc[16];
#pragma unroll
    for (int k = 0; k < 16; ++k) acc[k] = 0.f;
    float m = -INFINITY, l = 0.f;

    const int ngroups = (cnt + 1) >> 1;

    // stage group g into buffer g%3 (2 rows x 2 KB), evict-first in L2
    auto issue_group = [&](int g) {
        const int i0 = 2 * g;
        const int r0 = sm_rows[warp * 32 + i0];
        const int r1 = (i0 + 1 < cnt) ? sm_rows[warp * 32 + i0 + 1] : r0;
        char* buf = stage + (g % 3) * 4096;
        unsigned int s0 = (unsigned int)__cvta_generic_to_shared(buf) + lane * 16;
        const char* g0 = gbase + (size_t)r0 * 2048 + lane * 16;
        const char* g1 = gbase + (size_t)r1 * 2048 + lane * 16;
#pragma unroll
        for (int j = 0; j < 4; ++j) {
            asm volatile("cp.async.cg.shared.global.L2::cache_hint [%0], [%1], 16, %2;"
                         :: "r"(s0 + j * 512), "l"(g0 + j * 512), "l"(pol_ef));
            asm volatile("cp.async.cg.shared.global.L2::cache_hint [%0], [%1], 16, %2;"
                         :: "r"(s0 + 2048 + j * 512), "l"(g1 + j * 512), "l"(pol_ef));
        }
        asm volatile("cp.async.commit_group;" ::: "memory");
    };

    if (ngroups > 0) {
        issue_group(0);
        if (ngroups > 1) issue_group(1);

        for (int g = 0; g < ngroups; ++g) {
            if (g + 2 < ngroups) {
                issue_group(g + 2);
                asm volatile("cp.async.wait_group 2;" ::: "memory");
            } else if (g + 1 < ngroups) {
                asm volatile("cp.async.wait_group 1;" ::: "memory");
            } else {
                asm volatile("cp.async.wait_group 0;" ::: "memory");
            }
            __syncwarp();   // staged bytes visible across lanes

            const int i0 = 2 * g;
            const int r0 = sm_rows[warp * 32 + i0];
            const bool v1 = (i0 + 1) < cnt;
            const int r1 = v1 ? sm_rows[warp * 32 + i0 + 1] : r0;

            const float4* buf = (const float4*)(stage + (g % 3) * 4096);
            float4 v[2][4];
#pragma unroll
            for (int j = 0; j < 4; ++j) {
                v[0][j] = buf[lane + 32 * j];
                v[1][j] = buf[128 + lane + 32 * j];
            }

            float p0, p1;
            {
                float s0 = v[0][0].x*hv[0].x + v[0][0].y*hv[0].y + v[0][0].z*hv[0].z + v[0][0].w*hv[0].w;
                float s1 = v[0][1].x*hv[1].x + v[0][1].y*hv[1].y + v[0][1].z*hv[1].z + v[0][1].w*hv[1].w;
                float s2 = v[0][2].x*hv[2].x + v[0][2].y*hv[2].y + v[0][2].z*hv[2].z + v[0][2].w*hv[2].w;
                float s3 = v[0][3].x*hv[3].x + v[0][3].y*hv[3].y + v[0][3].z*hv[3].z + v[0][3].w*hv[3].w;
                p0 = (s0 + s1) + (s2 + s3);
            }
            {
                float s0 = v[1][0].x*hv[0].x + v[1][0].y*hv[0].y + v[1][0].z*hv[0].z + v[1][0].w*hv[0].w;
                float s1 = v[1][1].x*hv[1].x + v[1][1].y*hv[1].y + v[1][1].z*hv[1].z + v[1][1].w*hv[1].w;
                float s2 = v[1][2].x*hv[2].x + v[1][2].y*hv[2].y + v[1][2].z*hv[2].z + v[1][2].w*hv[2].w;
                float s3 = v[1][3].x*hv[3].x + v[1][3].y*hv[3].y + v[1][3].z*hv[3].z + v[1][3].w*hv[3].w;
                p1 = (s0 + s1) + (s2 + s3);
            }
#pragma unroll
            for (int off = 16; off; off >>= 1) {
                p0 += __shfl_xor_sync(0xffffffffu, p0, off);
                p1 += __shfl_xor_sync(0xffffffffu, p1, off);
            }

            const float gmax = v1 ? fmaxf(p0, p1) : p0;
            if (gmax > m) {
                const float sc = __expf(m - gmax);  // exp(-inf - x) = 0 first time
                l *= sc;
#pragma unroll
                for (int k = 0; k < 16; ++k) acc[k] *= sc;
                m = gmax;
            }
            const float e0 = __expf(p0 - m);
            const float e1 = v1 ? __expf(p1 - m) : 0.f;
            l += e0 + e1;
#pragma unroll
            for (int j = 0; j < 4; ++j) {
                acc[4*j+0] += e0 * v[0][j].x + e1 * v[1][j].x;
                acc[4*j+1] += e0 * v[0][j].y + e1 * v[1][j].y;
                acc[4*j+2] += e0 * v[0][j].z + e1 * v[1][j].z;
                acc[4*j+3] += e0 * v[0][j].w + e1 * v[1][j].w;
            }
            if (lane == 0) {
                sm_scores[warp * 32 + r0] = p0;
                if (v1) sm_scores[warp * 32 + r1] = p1;
            }
        }
    }

    __syncwarp();
    // coalesced score store (evict_last: k2 re-reads these)
    st_f32_el(&scores_out[(size_t)b * S_ + row0 + lane],
              sm_scores[warp * 32 + lane], pol_el);

    if (lane == 0) { sm_m[warp] = m; sm_l[warp] = l; }
    __syncthreads();   // all warps done with stage region -> sm_ctx alias safe

    // block max over the 8 warps
    float Mblk = -INFINITY;
#pragma unroll
    for (int w = 0; w < 8; ++w) Mblk = fmaxf(Mblk, sm_m[w]);

    // scale this warp's accumulator to the block max, dump to smem (float4)
    const float wscale = (m > -INFINITY) ? __expf(m - Mblk) : 0.f;
    float4* dst = (float4*)(sm_ctx + warp * H_);
#pragma unroll
    for (int j = 0; j < 4; ++j)
        dst[lane + 32 * j] = make_float4(acc[4*j+0] * wscale, acc[4*j+1] * wscale,
                                         acc[4*j+2] * wscale, acc[4*j+3] * wscale);
    __syncthreads();

    // reduce 8 warps -> per-tile partial context (evict_last stores)
    float* part = g_partial + (size_t)(b * NTILES + t) * H_;
    for (int h = tid; h < H_; h += 256) {
        float c = 0.f;
#pragma unroll
        for (int w = 0; w < 8; ++w) c += sm_ctx[w * H_ + h];
        st_f32_el(&part[h], c, pol_el);
    }

    if (tid == 0) {
        float L = 0.f;
#pragma unroll
        for (int w = 0; w < 8; ++w) {
            const float sc = (sm_m[w] > -INFINITY) ? __expf(sm_m[w] - Mblk) : 0.f;
            L += sm_l[w] * sc;
        }
        st_f32_el(&g_m[b * NTILES + t], Mblk, pol_el);
        st_f32_el(&g_l[b * NTILES + t], L, pol_el);
    }
}

// ---------------------------------------------------------------------------
// Per-batch (M, invT) from the tiny g_m/g_l arrays — warp 0, shfl reduce.
// NTILES == 32 fits the warp exactly.
// ---------------------------------------------------------------------------
__device__ __forceinline__ void batch_stats(int b, int tid,
                                            float* sh_M, float* sh_invT)
{
    if (tid < 32) {
        float mt = g_m[b * NTILES + tid];
        float lt = g_l[b * NTILES + tid];
        float Mb = mt;
#pragma unroll
        for (int off = 16; off; off >>= 1)
            Mb = fmaxf(Mb, __shfl_xor_sync(0xffffffffu, Mb, off));
        float c = (mt > -INFINITY) ? lt * __expf(mt - Mb) : 0.f;
#pragma unroll
        for (int off = 16; off; off >>= 1)
            c += __shfl_xor_sync(0xffffffffu, c, off);
        if (tid == 0) { *sh_M = Mb; *sh_invT = 1.f / c; }
    }
    __syncthreads();
}

// ---------------------------------------------------------------------------
// Kernel 2 (tail): grid (6, 64). slices 0,1 -> context combine halves;
// slices 2..5 -> weights quarters. Streaming loads PREFETCHED before the
// dependent batch_stats. With evict_last on k1's stores, these reads should
// now be L2 hits.
// ---------------------------------------------------------------------------
__global__ __launch_bounds__(256)
void k2_fused(float* __restrict__ ctx_out /* d_out */,
              float4* __restrict__ scores4 /* d_out + B*H */)
{
    const int slice = blockIdx.x;   // 0..5
    const int b     = blockIdx.y;
    const int tid   = threadIdx.x;

    __shared__ float sh_M, sh_invT;

    if (slice < 2) {
        // prefetch 32 tiles of g_partial at one h-position (32 indep loads)
        const int h = slice * 256 + tid;
        float part[NTILES];
#pragma unroll
        for (int t = 0; t < NTILES; ++t)
            part[t] = g_partial[(size_t)(b * NTILES + t) * H_ + h];
        __shared__ float sc[NTILES];
        batch_stats(b, tid, &sh_M, &sh_invT);
        if (tid < NTILES) {
            const float mt = g_m[b * NTILES + tid];
            sc[tid] = (mt > -INFINITY) ? __expf(mt - sh_M) : 0.f;
        }
        __syncthreads();
        const float iT = sh_invT;
        float c = 0.f;
#pragma unroll
        for (int t = 0; t < NTILES; ++t) c += part[t] * sc[t];
        ctx_out[(size_t)b * H_ + h] = c * iT;
    } else {
        // prefetch the 2 float4 per thread, then stats, then exp+store
        float4* p = scores4 + (size_t)b * (S_ / 4) + (slice - 2) * 512;
        float4 s0 = p[tid];
        float4 s1 = p[tid + 256];
        batch_stats(b, tid, &sh_M, &sh_invT);
        const float M  = sh_M;
        const float iT = sh_invT;
        s0.x = __expf(s0.x - M) * iT;  s0.y = __expf(s0.y - M) * iT;
        s0.z = __expf(s0.z - M) * iT;  s0.w = __expf(s0.w - M) * iT;
        s1.x = __expf(s1.x - M) * iT;  s1.y = __expf(s1.y - M) * iT;
        s1.z = __expf(s1.z - M) * iT;  s1.w = __expf(s1.w - M) * iT;
        p[tid]       = s0;
        p[tid + 256] = s1;
    }
}

// ---------------------------------------------------------------------------
extern "C" void kernel_launch(void* const* d_in, const int* in_sizes, int n_in,
                              void* d_out, int out_size)
{
    const float* hid  = (const float*)d_in[0];   // [B,H]
    const float* enc  = (const float*)d_in[1];   // [B,S,H]
    const void*  mask = d_in[2];                 // [B,S] bool (width detected)

    float* ctx     = (float*)d_out;            // [B,H]
    float* weights = (float*)d_out + B_ * H_;  // [B,S]

    static bool attr_set = false;
    if (!attr_set) {
        cudaFuncSetAttribute(k1_scores_partials,
                             cudaFuncAttributeMaxDynamicSharedMemorySize,
                             SMEM_TOTAL);
        attr_set = true;
    }

    k1_scores_partials<<<NBLOCKS1, 256, SMEM_TOTAL>>>(hid, enc, mask, weights);
    k2_fused<<<dim3(6, B_), 256>>>(ctx, (float4*)weights);
}

// round 17
// speedup vs baseline: 1.0053x; 1.0053x over previous
#include <cuda_runtime.h>
#include <math.h>

// Problem constants (fixed by the reference)
#define B_  64
#define S_  8192
#define H_  512
#define STILE 256
#define NTILES (S_ / STILE)    // 32
#define NBLOCKS1 (B_ * NTILES) // 2048

// Scratch (allocation-free: __device__ globals)
__device__ float g_partial[B_ * NTILES * H_];  // 4 MB
__device__ float g_m[B_ * NTILES];
__device__ float g_l[B_ * NTILES];

// Dynamic smem layout (bytes). sm_ctx (16 KB) is ALIASED into the stage
// region: only touched after the main loop, past a __syncthreads(), when all
// cp.async traffic has drained.
#define OFF_HID     0                         // 2048  (128 float4)
#define OFF_SCORES  2048                      // 1024  (8 x 32 floats)
#define OFF_ROWS    3072                      // 256   (8 x 32 bytes)
#define OFF_M       3328                      // 32
#define OFF_L       3360                      // 32
#define OFF_FLAG    3392                      // 32
#define OFF_STAGE   3456                      // 128-aligned
#define STAGE_PER_WARP 12288                  // 3 bufs x 2 rows x 2048 B
#define SMEM_TOTAL  (OFF_STAGE + 8 * STAGE_PER_WARP)  // 101760 B (~99.4 KB)

// ---------------------------------------------------------------------------
// Kernel 1 (hot path frozen since R9; fusion permanently locked out).
// One block per (batch, 256-row S-tile). Each warp owns 32 rows; active rows
// compacted via ballot+popc; triple-buffered cp.async pipeline with L2
// evict_first on the single-use encoder stream (R15 win).
// NEW: odd-count tail groups stage only ONE row (previously the duplicated
// filler row was re-streamed from HBM — ~1.5% wasted encoder traffic).
// ---------------------------------------------------------------------------
__global__ __launch_bounds__(256)
void k1_scores_partials(const float* __restrict__ hid,
                        const float* __restrict__ enc,
                        const void* __restrict__ mask,
                        float* __restrict__ scores_out /* = d_out + B*H */)
{
    extern __shared__ char dsm[];
    float4*        sh_hid    = (float4*)(dsm + OFF_HID);
    float*         sm_scores = (float*)(dsm + OFF_SCORES);
    unsigned char* sm_rows   = (unsigned char*)(dsm + OFF_ROWS);
    float*         sm_m      = (float*)(dsm + OFF_M);
    float*         sm_l      = (float*)(dsm + OFF_L);
    int*           sh_flag   = (int*)(dsm + OFF_FLAG);
    float*         sm_ctx    = (float*)(dsm + OFF_STAGE);   // ALIASED w/ stage

    const int b = blockIdx.x / NTILES;
    const int t = blockIdx.x % NTILES;
    const int tid  = threadIdx.x;
    const int warp = tid >> 5;
    const int lane = tid & 31;

    // L2 evict-first policy for the single-use encoder stream
    unsigned long long pol_ef;
    asm("createpolicy.fractional.L2::evict_first.b64 %0, 1.0;" : "=l"(pol_ef));

    // decoder_hidden[b,:] -> smem
    {
        const float4* h4 = (const float4*)(hid + (size_t)b * H_);
        if (tid < H_ / 4) sh_hid[tid] = h4[tid];
    }
    sm_scores[warp * 32 + lane] = -INFINITY;

    // mask width detection: branch-free OR over first 512 words (safe under
    // both layouts; byte-bools give a word>1 with prob 1-(1/8)^512 ~ 1)
    {
        const unsigned int* mw = (const unsigned int*)mask;
        unsigned int v = mw[tid] | mw[tid + 256];
        unsigned any = __any_sync(0xffffffffu, v > 1u);
        if (lane == 0) sh_flag[warp] = any ? 1 : 0;
    }
    __syncthreads();
    const int mask_is_byte = sh_flag[0] | sh_flag[1] | sh_flag[2] | sh_flag[3]
                           | sh_flag[4] | sh_flag[5] | sh_flag[6] | sh_flag[7];

    float4 hv[4];
#pragma unroll
    for (int j = 0; j < 4; ++j) hv[j] = sh_hid[lane + 32 * j];

    // this warp's 32 rows: ballot + parallel compaction into sm_rows
    const int row0 = t * STILE + warp * 32;
    bool keep;
    if (mask_is_byte)
        keep = ((const unsigned char*)mask)[(size_t)b * S_ + row0 + lane] != 0;
    else
        keep = ((const int*)mask)[(size_t)b * S_ + row0 + lane] != 0;
    const unsigned b0 = __ballot_sync(0xffffffffu, keep);
    const unsigned lmask = (lane == 31) ? 0x7fffffffu : ((1u << lane) - 1u);
    if (keep) sm_rows[warp * 32 + __popc(b0 & lmask)] = (unsigned char)lane;
    const int cnt = __popc(b0);
    __syncwarp();

    const char* gbase = (const char*)(enc + ((size_t)b * S_ + row0) * H_);
    char* stage = dsm + OFF_STAGE + warp * STAGE_PER_WARP;

    float acc[16];
#pragma unroll
    for (int k = 0; k < 16; ++k) acc[k] = 0.f;
    float m = -INFINITY, l = 0.f;

    const int ngroups = (cnt + 1) >> 1;

    // stage group g into buffer g%3. Full groups: 2 rows (4 KB); an odd
    // tail group stages only its single live row (2 KB) — no filler stream.
    auto issue_group = [&](int g) {
        const int i0 = 2 * g;
        const int r0 = sm_rows[warp * 32 + i0];
        const bool two = (i0 + 1) < cnt;
        char* buf = stage + (g % 3) * 4096;
        unsigned int s0 = (unsigned int)__cvta_generic_to_shared(buf) + lane * 16;
        const char* g0 = gbase + (size_t)r0 * 2048 + lane * 16;
#pragma unroll
        for (int j = 0; j < 4; ++j)
            asm volatile("cp.async.cg.shared.global.L2::cache_hint [%0], [%1], 16, %2;"
                         :: "r"(s0 + j * 512), "l"(g0 + j * 512), "l"(pol_ef));
        if (two) {
            const int r1 = sm_rows[warp * 32 + i0 + 1];
            const char* g1 = gbase + (size_t)r1 * 2048 + lane * 16;
#pragma unroll
            for (int j = 0; j < 4; ++j)
                asm volatile("cp.async.cg.shared.global.L2::cache_hint [%0], [%1], 16, %2;"
                             :: "r"(s0 + 2048 + j * 512), "l"(g1 + j * 512), "l"(pol_ef));
        }
        asm volatile("cp.async.commit_group;" ::: "memory");
    };

    if (ngroups > 0) {
        issue_group(0);
        if (ngroups > 1) issue_group(1);

        for (int g = 0; g < ngroups; ++g) {
            if (g + 2 < ngroups) {
                issue_group(g + 2);
                asm volatile("cp.async.wait_group 2;" ::: "memory");
            } else if (g + 1 < ngroups) {
                asm volatile("cp.async.wait_group 1;" ::: "memory");
            } else {
                asm volatile("cp.async.wait_group 0;" ::: "memory");
            }
            __syncwarp();   // staged bytes visible across lanes

            const int i0 = 2 * g;
            const int r0 = sm_rows[warp * 32 + i0];
            const bool v1 = (i0 + 1) < cnt;
            const int r1 = v1 ? sm_rows[warp * 32 + i0 + 1] : r0;

            const float4* buf = (const float4*)(stage + (g % 3) * 4096);
            float4 v[2][4];
#pragma unroll
            for (int j = 0; j < 4; ++j) v[0][j] = buf[lane + 32 * j];
            if (v1) {
#pragma unroll
                for (int j = 0; j < 4; ++j) v[1][j] = buf[128 + lane + 32 * j];
            } else {
#pragma unroll
                for (int j = 0; j < 4; ++j) v[1][j] = make_float4(0.f, 0.f, 0.f, 0.f);
            }

            float p0, p1;
            {
                float s0 = v[0][0].x*hv[0].x + v[0][0].y*hv[0].y + v[0][0].z*hv[0].z + v[0][0].w*hv[0].w;
                float s1 = v[0][1].x*hv[1].x + v[0][1].y*hv[1].y + v[0][1].z*hv[1].z + v[0][1].w*hv[1].w;
                float s2 = v[0][2].x*hv[2].x + v[0][2].y*hv[2].y + v[0][2].z*hv[2].z + v[0][2].w*hv[2].w;
                float s3 = v[0][3].x*hv[3].x + v[0][3].y*hv[3].y + v[0][3].z*hv[3].z + v[0][3].w*hv[3].w;
                p0 = (s0 + s1) + (s2 + s3);
            }
            {
                float s0 = v[1][0].x*hv[0].x + v[1][0].y*hv[0].y + v[1][0].z*hv[0].z + v[1][0].w*hv[0].w;
                float s1 = v[1][1].x*hv[1].x + v[1][1].y*hv[1].y + v[1][1].z*hv[1].z + v[1][1].w*hv[1].w;
                float s2 = v[1][2].x*hv[2].x + v[1][2].y*hv[2].y + v[1][2].z*hv[2].z + v[1][2].w*hv[2].w;
                float s3 = v[1][3].x*hv[3].x + v[1][3].y*hv[3].y + v[1][3].z*hv[3].z + v[1][3].w*hv[3].w;
                p1 = (s0 + s1) + (s2 + s3);
            }
#pragma unroll
            for (int off = 16; off; off >>= 1) {
                p0 += __shfl_xor_sync(0xffffffffu, p0, off);
                p1 += __shfl_xor_sync(0xffffffffu, p1, off);
            }

            const float gmax = v1 ? fmaxf(p0, p1) : p0;
            if (gmax > m) {
                const float sc = __expf(m - gmax);  // exp(-inf - x) = 0 first time
                l *= sc;
#pragma unroll
                for (int k = 0; k < 16; ++k) acc[k] *= sc;
                m = gmax;
            }
            const float e0 = __expf(p0 - m);
            const float e1 = v1 ? __expf(p1 - m) : 0.f;
            l += e0 + e1;
#pragma unroll
            for (int j = 0; j < 4; ++j) {
                acc[4*j+0] += e0 * v[0][j].x + e1 * v[1][j].x;
                acc[4*j+1] += e0 * v[0][j].y + e1 * v[1][j].y;
                acc[4*j+2] += e0 * v[0][j].z + e1 * v[1][j].z;
                acc[4*j+3] += e0 * v[0][j].w + e1 * v[1][j].w;
            }
            if (lane == 0) {
                sm_scores[warp * 32 + r0] = p0;
                if (v1) sm_scores[warp * 32 + r1] = p1;
            }
        }
    }

    __syncwarp();
    // coalesced score store
    scores_out[(size_t)b * S_ + row0 + lane] = sm_scores[warp * 32 + lane];

    if (lane == 0) { sm_m[warp] = m; sm_l[warp] = l; }
    __syncthreads();   // all warps done with stage region -> sm_ctx alias safe

    // block max over the 8 warps
    float Mblk = -INFINITY;
#pragma unroll
    for (int w = 0; w < 8; ++w) Mblk = fmaxf(Mblk, sm_m[w]);

    // scale this warp's accumulator to the block max, dump to smem (float4)
    const float wscale = (m > -INFINITY) ? __expf(m - Mblk) : 0.f;
    float4* dst = (float4*)(sm_ctx + warp * H_);
#pragma unroll
    for (int j = 0; j < 4; ++j)
        dst[lane + 32 * j] = make_float4(acc[4*j+0] * wscale, acc[4*j+1] * wscale,
                                         acc[4*j+2] * wscale, acc[4*j+3] * wscale);
    __syncthreads();

    // reduce 8 warps -> per-tile partial context
    float* part = g_partial + (size_t)(b * NTILES + t) * H_;
    for (int h = tid; h < H_; h += 256) {
        float c = 0.f;
#pragma unroll
        for (int w = 0; w < 8; ++w) c += sm_ctx[w * H_ + h];
        part[h] = c;
    }

    if (tid == 0) {
        float L = 0.f;
#pragma unroll
        for (int w = 0; w < 8; ++w) {
            const float sc = (sm_m[w] > -INFINITY) ? __expf(sm_m[w] - Mblk) : 0.f;
            L += sm_l[w] * sc;
        }
        g_m[b * NTILES + t] = Mblk;
        g_l[b * NTILES + t] = L;
    }
}

// ---------------------------------------------------------------------------
// Per-batch (M, invT) from the tiny g_m/g_l arrays — warp 0, shfl reduce.
// NTILES == 32 fits the warp exactly.
// ---------------------------------------------------------------------------
__device__ __forceinline__ void batch_stats(int b, int tid,
                                            float* sh_M, float* sh_invT)
{
    if (tid < 32) {
        float mt = g_m[b * NTILES + tid];
        float lt = g_l[b * NTILES + tid];
        float Mb = mt;
#pragma unroll
        for (int off = 16; off; off >>= 1)
            Mb = fmaxf(Mb, __shfl_xor_sync(0xffffffffu, Mb, off));
        float c = (mt > -INFINITY) ? lt * __expf(mt - Mb) : 0.f;
#pragma unroll
        for (int off = 16; off; off >>= 1)
            c += __shfl_xor_sync(0xffffffffu, c, off);
        if (tid == 0) { *sh_M = Mb; *sh_invT = 1.f / c; }
    }
    __syncthreads();
}

// ---------------------------------------------------------------------------
// Kernel 2 (tail): grid (6, 64). slices 0,1 -> context combine halves;
// slices 2..5 -> weights quarters. Streaming loads PREFETCHED before the
// dependent batch_stats so the stats latency hides under them.
// ---------------------------------------------------------------------------
__global__ __launch_bounds__(256)
void k2_fused(float* __restrict__ ctx_out /* d_out */,
              float4* __restrict__ scores4 /* d_out + B*H */)
{
    const int slice = blockIdx.x;   // 0..5
    const int b     = blockIdx.y;
    const int tid   = threadIdx.x;

    __shared__ float sh_M, sh_invT;

    if (slice < 2) {
        // prefetch 32 tiles of g_partial at one h-position (32 indep loads)
        const int h = slice * 256 + tid;
        float part[NTILES];
#pragma unroll
        for (int t = 0; t < NTILES; ++t)
            part[t] = g_partial[(size_t)(b * NTILES + t) * H_ + h];
        __shared__ float sc[NTILES];
        batch_stats(b, tid, &sh_M, &sh_invT);
        if (tid < NTILES) {
            const float mt = g_m[b * NTILES + tid];
            sc[tid] = (mt > -INFINITY) ? __expf(mt - sh_M) : 0.f;
        }
        __syncthreads();
        const float iT = sh_invT;
        float c = 0.f;
#pragma unroll
        for (int t = 0; t < NTILES; ++t) c += part[t] * sc[t];
        ctx_out[(size_t)b * H_ + h] = c * iT;
    } else {
        // prefetch the 2 float4 per thread, then stats, then exp+store
        float4* p = scores4 + (size_t)b * (S_ / 4) + (slice - 2) * 512;
        float4 s0 = p[tid];
        float4 s1 = p[tid + 256];
        batch_stats(b, tid, &sh_M, &sh_invT);
        const float M  = sh_M;
        const float iT = sh_invT;
        s0.x = __expf(s0.x - M) * iT;  s0.y = __expf(s0.y - M) * iT;
        s0.z = __expf(s0.z - M) * iT;  s0.w = __expf(s0.w - M) * iT;
        s1.x = __expf(s1.x - M) * iT;  s1.y = __expf(s1.y - M) * iT;
        s1.z = __expf(s1.z - M) * iT;  s1.w = __expf(s1.w - M) * iT;
        p[tid]       = s0;
        p[tid + 256] = s1;
    }
}

// ---------------------------------------------------------------------------
extern "C" void kernel_launch(void* const* d_in, const int* in_sizes, int n_in,
                              void* d_out, int out_size)
{
    const float* hid  = (const float*)d_in[0];   // [B,H]
    const float* enc  = (const float*)d_in[1];   // [B,S,H]
    const void*  mask = d_in[2];                 // [B,S] bool (width detected)

    float* ctx     = (float*)d_out;            // [B,H]
    float* weights = (float*)d_out + B_ * H_;  // [B,S]

    static bool attr_set = false;
    if (!attr_set) {
        cudaFuncSetAttribute(k1_scores_partials,
                             cudaFuncAttributeMaxDynamicSharedMemorySize,
                             SMEM_TOTAL);
        attr_set = true;
    }

    k1_scores_partials<<<NBLOCKS1, 256, SMEM_TOTAL>>>(hid, enc, mask, weights);
    k2_fused<<<dim3(6, B_), 256>>>(ctx, (float4*)weights);
}